// round 1
// baseline (speedup 1.0000x reference)
#include <cuda_runtime.h>
#include <math.h>
#include <stdint.h>

#define NN   100000
#define EE   1600000
#define HID  128
#define HEADS 4
#define HDIM  32
#define NEG  0.2f
#define LNEPS 1e-5f

// ---------------- device scratch (no allocation allowed) ----------------
__device__ __align__(256) float g_h   [(size_t)NN*HID];
__device__ __align__(256) float g_agg [(size_t)NN*HID];
__device__ __align__(256) float g_xe8 [(size_t)NN*HID];
__device__ __align__(256) float g_gg  [(size_t)NN*HID];   // GAT transformed features
__device__ __align__(256) float g_xgat[(size_t)NN*HID];
__device__ __align__(256) float g_z   [(size_t)NN*HID];
__device__ __align__(16)  float g_asrc[(size_t)NN*HEADS];
__device__ __align__(16)  float g_adst[(size_t)NN*HEADS];
__device__ float g_dinv[NN];
__device__ int   g_cnt_row[NN];
__device__ int   g_cnt_col[NN];
__device__ int   g_rptr[NN+1];
__device__ int   g_cptr[NN+1];
__device__ int   g_rcur[NN];
__device__ int   g_ccur[NN];
__device__ int   g_csr_rc[EE];   // row-CSR payload: col per slot
__device__ int   g_csr_cs[EE];   // col-CSR payload: src per slot
__device__ int   g_shift;        // 0: edge_index int32, 1: int64 (low words)

// ---------------- helpers ----------------
__device__ __forceinline__ float wsum(float x){
    #pragma unroll
    for (int o=16;o;o>>=1) x += __shfl_xor_sync(0xffffffffu, x, o);
    return x;
}
__device__ __forceinline__ float wmax(float x){
    #pragma unroll
    for (int o=16;o;o>>=1) x = fmaxf(x, __shfl_xor_sync(0xffffffffu, x, o));
    return x;
}
__device__ __forceinline__ float lrelu(float x){
    return x > 0.f ? x : NEG * x;
}

// ---------------- dtype detection ----------------
__global__ void k_detect(const int* ei){
    if (threadIdx.x == 0){
        int acc = 0;
        #pragma unroll 1
        for (int i = 1; i < 128; i += 2) acc |= ei[i];
        g_shift = (acc == 0) ? 1 : 0;   // int64 LE: high words of small values are 0
    }
}

__global__ void k_zero(){
    int i = blockIdx.x*blockDim.x + threadIdx.x;
    if (i < NN){ g_cnt_row[i]=0; g_cnt_col[i]=0; }
}

__global__ void k_hist(const int* ei){
    int e = blockIdx.x*blockDim.x + threadIdx.x;
    if (e >= EE) return;
    int sh = g_shift;
    int r = ei[(size_t)e << sh];
    int c = ei[(size_t)(EE + e) << sh];
    atomicAdd(&g_cnt_row[r], 1);
    atomicAdd(&g_cnt_col[c], 1);
}

// 2 blocks x 1024 threads: block 0 scans row counts, block 1 scans col counts
__global__ void k_scan(){
    const int* cnt = blockIdx.x ? g_cnt_col : g_cnt_row;
    int* ptr = blockIdx.x ? g_cptr : g_rptr;
    int* cur = blockIdx.x ? g_ccur : g_rcur;
    __shared__ int sh[1024];
    __shared__ int carryS;
    int tid = threadIdx.x;
    int carry = 0;
    for (int base = 0; base < NN; base += 1024){
        int i = base + tid;
        int v = (i < NN) ? cnt[i] : 0;
        sh[tid] = v; __syncthreads();
        #pragma unroll
        for (int off = 1; off < 1024; off <<= 1){
            int t = (tid >= off) ? sh[tid-off] : 0;
            __syncthreads();
            sh[tid] += t;
            __syncthreads();
        }
        int inc = sh[tid];
        if (i < NN){ int ex = carry + inc - v; ptr[i] = ex; cur[i] = ex; }
        if (tid == 1023) carryS = carry + inc;
        __syncthreads();
        carry = carryS;
        __syncthreads();
    }
    if (tid == 0) ptr[NN] = carry;
}

__global__ void k_fill(const int* ei){
    int e = blockIdx.x*blockDim.x + threadIdx.x;
    if (e >= EE) return;
    int sh = g_shift;
    int r = ei[(size_t)e << sh];
    int c = ei[(size_t)(EE + e) << sh];
    int p = atomicAdd(&g_rcur[r], 1);
    g_csr_rc[p] = c;
    int q = atomicAdd(&g_ccur[c], 1);
    g_csr_cs[q] = r;
}

__global__ void k_dinv(){
    int i = blockIdx.x*blockDim.x + threadIdx.x;
    if (i < NN){
        int d = g_cnt_col[i];
        g_dinv[i] = d > 0 ? rsqrtf((float)d) : 0.f;
    }
}

// ---------------- generic 128-col GEMM: C[N,128] = A[N,K] @ W[128,K]^T (+bias) (+LN epi) ----
// block: 256 thr, 64 rows; warp owns 8 rows x 128 cols (lane covers cols lane+32j)
template<int K, int EPI>
__global__ __launch_bounds__(256)
void k_gemm(const float* __restrict__ A0, const float* __restrict__ A1,
            const float* __restrict__ W,  const float* __restrict__ bias,
            const float* __restrict__ res, const float* __restrict__ gamma,
            const float* __restrict__ beta, float* __restrict__ C)
{
    extern __shared__ float smem[];
    float* Ws = smem;              // [K][132] transposed, padded
    float* As = smem + K*132;      // [64][K]
    int tid  = threadIdx.x;
    int row0 = blockIdx.x * 64;

    // W load (global coalesced; STS 4-way conflict acceptable, one-time)
    for (int idx = tid; idx < 128*K; idx += 256){
        int o = idx / K, k = idx - o*K;
        Ws[k*132 + o] = W[idx];
    }
    // A load (coalesced both sides)
    for (int idx = tid; idx < 64*K; idx += 256){
        int r = idx / K, k = idx - r*K;
        int gr = row0 + r;
        float v = 0.f;
        if (gr < NN){
            if (K == 256) v = (k < 128) ? A0[(size_t)gr*128 + k] : A1[(size_t)gr*128 + (k-128)];
            else          v = A0[(size_t)gr*K + k];
        }
        As[idx] = v;
    }
    __syncthreads();

    int lane = tid & 31, warp = tid >> 5;
    int r0 = warp * 8;

    float acc[8][4];
    #pragma unroll
    for (int i = 0; i < 8; i++)
        #pragma unroll
        for (int j = 0; j < 4; j++)
            acc[i][j] = bias ? bias[lane + 32*j] : 0.f;

    #pragma unroll 4
    for (int k = 0; k < K; k++){
        float w0 = Ws[k*132 + lane];
        float w1 = Ws[k*132 + lane + 32];
        float w2 = Ws[k*132 + lane + 64];
        float w3 = Ws[k*132 + lane + 96];
        #pragma unroll
        for (int i = 0; i < 8; i++){
            float a = As[(r0+i)*K + k];
            acc[i][0] = fmaf(a, w0, acc[i][0]);
            acc[i][1] = fmaf(a, w1, acc[i][1]);
            acc[i][2] = fmaf(a, w2, acc[i][2]);
            acc[i][3] = fmaf(a, w3, acc[i][3]);
        }
    }

    if (EPI == 0){
        #pragma unroll
        for (int i = 0; i < 8; i++){
            int gr = row0 + r0 + i;
            if (gr < NN){
                #pragma unroll
                for (int j = 0; j < 4; j++)
                    C[(size_t)gr*128 + lane + 32*j] = acc[i][j];
            }
        }
    } else {
        // z = acc + res;  LayerNorm(gamma,beta);  ReLU
        #pragma unroll
        for (int i = 0; i < 8; i++){
            int gr = row0 + r0 + i;
            if (gr >= NN) continue;   // uniform per warp
            float v[4];
            #pragma unroll
            for (int j = 0; j < 4; j++)
                v[j] = acc[i][j] + res[(size_t)gr*128 + lane + 32*j];
            float s = v[0]+v[1]+v[2]+v[3];
            float mu = wsum(s) * (1.f/128.f);
            float q = 0.f;
            #pragma unroll
            for (int j = 0; j < 4; j++){ float d = v[j]-mu; q = fmaf(d,d,q); }
            float var = wsum(q) * (1.f/128.f);
            float sc = rsqrtf(var + LNEPS);
            #pragma unroll
            for (int j = 0; j < 4; j++){
                int c = lane + 32*j;
                float o = (v[j]-mu)*sc*gamma[c] + beta[c];
                C[(size_t)gr*128 + c] = fmaxf(o, 0.f);
            }
        }
    }
}

// ---------------- attention logits: a_src/a_dst [N,4] ----------------
__global__ void k_att(const float* __restrict__ att_src, const float* __restrict__ att_dst){
    int t = blockIdx.x*blockDim.x + threadIdx.x;
    if (t >= NN*HEADS) return;
    int n = t >> 2, h = t & 3;
    const float* gp = &g_gg[(size_t)n*128 + h*32];
    float s = 0.f, d = 0.f;
    #pragma unroll
    for (int c = 0; c < 32; c++){
        float gv = gp[c];
        s = fmaf(gv, att_src[h*32+c], s);
        d = fmaf(gv, att_dst[h*32+c], d);
    }
    g_asrc[t] = s; g_adst[t] = d;
}

// ---------------- E8 aggregation: warp per node over row-CSR ----------------
__global__ void k_e8agg(){
    int w = (blockIdx.x*blockDim.x + threadIdx.x) >> 5;
    if (w >= NN) return;
    int lane = threadIdx.x & 31;
    int s = g_rptr[w], e = g_rptr[w+1];
    float4 acc = make_float4(0.f,0.f,0.f,0.f);
    for (int i = s; i < e; i++){
        int c = g_csr_rc[i];
        float dv = g_dinv[c];
        float4 hv = ((const float4*)(g_h + (size_t)c*128))[lane];
        acc.x = fmaf(dv, hv.x, acc.x);
        acc.y = fmaf(dv, hv.y, acc.y);
        acc.z = fmaf(dv, hv.z, acc.z);
        acc.w = fmaf(dv, hv.w, acc.w);
    }
    float du = g_dinv[w];
    float4 o = make_float4(du*acc.x, du*acc.y, du*acc.z, du*acc.w);
    ((float4*)(g_agg + (size_t)w*128))[lane] = o;
}

// ---------------- GAT: warp per destination node over col-CSR + self loop ------
__global__ void k_gat(const float* __restrict__ bgat){
    int v = (blockIdx.x*blockDim.x + threadIdx.x) >> 5;
    if (v >= NN) return;
    int lane = threadIdx.x & 31;
    int s = g_cptr[v], e = g_cptr[v+1];

    float4 ad = ((const float4*)g_adst)[v];
    float4 asl = ((const float4*)g_asrc)[v];
    float es0 = lrelu(asl.x + ad.x), es1 = lrelu(asl.y + ad.y);
    float es2 = lrelu(asl.z + ad.z), es3 = lrelu(asl.w + ad.w);

    // pass 1: max
    float m0 = es0, m1 = es1, m2 = es2, m3 = es3;
    for (int i = s + lane; i < e; i += 32){
        int u = g_csr_cs[i];
        float4 a = ((const float4*)g_asrc)[u];
        m0 = fmaxf(m0, lrelu(a.x + ad.x));
        m1 = fmaxf(m1, lrelu(a.y + ad.y));
        m2 = fmaxf(m2, lrelu(a.z + ad.z));
        m3 = fmaxf(m3, lrelu(a.w + ad.w));
    }
    m0 = wmax(m0); m1 = wmax(m1); m2 = wmax(m2); m3 = wmax(m3);

    // pass 2: sum exp
    float s0=0.f,s1=0.f,s2=0.f,s3=0.f;
    for (int i = s + lane; i < e; i += 32){
        int u = g_csr_cs[i];
        float4 a = ((const float4*)g_asrc)[u];
        s0 += __expf(lrelu(a.x + ad.x) - m0);
        s1 += __expf(lrelu(a.y + ad.y) - m1);
        s2 += __expf(lrelu(a.z + ad.z) - m2);
        s3 += __expf(lrelu(a.w + ad.w) - m3);
    }
    s0 = wsum(s0) + __expf(es0 - m0);
    s1 = wsum(s1) + __expf(es1 - m1);
    s2 = wsum(s2) + __expf(es2 - m2);
    s3 = wsum(s3) + __expf(es3 - m3);
    float i0 = 1.f/(s0+1e-16f), i1 = 1.f/(s1+1e-16f), i2 = 1.f/(s2+1e-16f), i3 = 1.f/(s3+1e-16f);

    // pass 3: weighted message accumulate. lane covers dims [4*lane,4*lane+4) -> head = lane/8
    int hidx = lane >> 3;
    float adh  = (hidx==0)?ad.x : (hidx==1)?ad.y : (hidx==2)?ad.z : ad.w;
    float mh   = (hidx==0)?m0  : (hidx==1)?m1  : (hidx==2)?m2  : m3;
    float ih   = (hidx==0)?i0  : (hidx==1)?i1  : (hidx==2)?i2  : i3;
    float esh  = (hidx==0)?es0 : (hidx==1)?es1 : (hidx==2)?es2 : es3;

    float4 acc = make_float4(0.f,0.f,0.f,0.f);
    for (int i = s; i < e; i++){
        int u = g_csr_cs[i];
        float a = g_asrc[(size_t)u*4 + hidx];
        float alpha = __expf(lrelu(a + adh) - mh) * ih;
        float4 gv = ((const float4*)(g_gg + (size_t)u*128))[lane];
        acc.x = fmaf(alpha, gv.x, acc.x);
        acc.y = fmaf(alpha, gv.y, acc.y);
        acc.z = fmaf(alpha, gv.z, acc.z);
        acc.w = fmaf(alpha, gv.w, acc.w);
    }
    {   // self loop
        float alpha = __expf(esh - mh) * ih;
        float4 gv = ((const float4*)(g_gg + (size_t)v*128))[lane];
        acc.x = fmaf(alpha, gv.x, acc.x);
        acc.y = fmaf(alpha, gv.y, acc.y);
        acc.z = fmaf(alpha, gv.z, acc.z);
        acc.w = fmaf(alpha, gv.w, acc.w);
    }
    float4 b = ((const float4*)bgat)[lane];
    acc.x += b.x; acc.y += b.y; acc.z += b.z; acc.w += b.w;
    ((float4*)(g_xgat + (size_t)v*128))[lane] = acc;
}

// ---------------- fused readout: sigmoid(relu(z@Wr1^T+b1)@Wr2^T+b2) -------------
__global__ __launch_bounds__(1024)
void k_readout(const float* __restrict__ Wr1, const float* __restrict__ br1,
               const float* __restrict__ Wr2, const float* __restrict__ br2,
               float* __restrict__ out)
{
    __shared__ float Ws[128*65];   // [k][o] padded
    int tid = threadIdx.x;
    for (int idx = tid; idx < 64*128; idx += 1024){
        int o = idx >> 7, k = idx & 127;
        Ws[k*65 + o] = Wr1[idx];
    }
    __syncthreads();
    int warp = tid >> 5, lane = tid & 31;
    int node = blockIdx.x*32 + warp;
    if (node >= NN) return;

    float4 zv = ((const float4*)(g_z + (size_t)node*128))[lane];
    float a0 = 0.f, a1 = 0.f;
    #pragma unroll 8
    for (int kb = 0; kb < 32; kb++){
        float zx = __shfl_sync(0xffffffffu, zv.x, kb);
        float zy = __shfl_sync(0xffffffffu, zv.y, kb);
        float zz = __shfl_sync(0xffffffffu, zv.z, kb);
        float zw = __shfl_sync(0xffffffffu, zv.w, kb);
        int k = kb*4;
        a0 = fmaf(zx, Ws[(k+0)*65+lane],    a0); a1 = fmaf(zx, Ws[(k+0)*65+lane+32], a1);
        a0 = fmaf(zy, Ws[(k+1)*65+lane],    a0); a1 = fmaf(zy, Ws[(k+1)*65+lane+32], a1);
        a0 = fmaf(zz, Ws[(k+2)*65+lane],    a0); a1 = fmaf(zz, Ws[(k+2)*65+lane+32], a1);
        a0 = fmaf(zw, Ws[(k+3)*65+lane],    a0); a1 = fmaf(zw, Ws[(k+3)*65+lane+32], a1);
    }
    float r0 = fmaxf(a0 + br1[lane],     0.f);
    float r1 = fmaxf(a1 + br1[lane+32],  0.f);
    float p = fmaf(r0, Wr2[lane], r1 * Wr2[lane+32]);
    p = wsum(p);
    if (lane == 0){
        float x = p + br2[0];
        out[node] = 1.f / (1.f + __expf(-x));
    }
}

// ---------------- host ----------------
extern "C" void kernel_launch(void* const* d_in, const int* in_sizes, int n_in,
                              void* d_out, int out_size)
{
    const float* x       = (const float*)d_in[0];
    const int*   ei      = (const int*)  d_in[1];
    const float* W_emb   = (const float*)d_in[2];
    const float* b_emb   = (const float*)d_in[3];
    const float* W_e8    = (const float*)d_in[4];
    const float* W_gat   = (const float*)d_in[5];
    const float* att_src = (const float*)d_in[6];
    const float* att_dst = (const float*)d_in[7];
    const float* b_gat   = (const float*)d_in[8];
    const float* W_fus   = (const float*)d_in[9];
    const float* b_fus   = (const float*)d_in[10];
    const float* gamma   = (const float*)d_in[11];
    const float* beta    = (const float*)d_in[12];
    const float* W_r1    = (const float*)d_in[13];
    const float* b_r1    = (const float*)d_in[14];
    const float* W_r2    = (const float*)d_in[15];
    const float* b_r2    = (const float*)d_in[16];
    float* out = (float*)d_out;

    float *h, *agg, *xe8, *gg, *xgat, *z;
    cudaGetSymbolAddress((void**)&h,    g_h);
    cudaGetSymbolAddress((void**)&agg,  g_agg);
    cudaGetSymbolAddress((void**)&xe8,  g_xe8);
    cudaGetSymbolAddress((void**)&gg,   g_gg);
    cudaGetSymbolAddress((void**)&xgat, g_xgat);
    cudaGetSymbolAddress((void**)&z,    g_z);

    int sm128 = (128*132 + 64*128) * 4;
    int sm256 = (256*132 + 64*256) * 4;
    cudaFuncSetAttribute(k_gemm<128,0>, cudaFuncAttributeMaxDynamicSharedMemorySize, sm128);
    cudaFuncSetAttribute(k_gemm<256,1>, cudaFuncAttributeMaxDynamicSharedMemorySize, sm256);

    int gB = (NN + 63) / 64;

    k_detect<<<1, 32>>>(ei);
    k_zero  <<<(NN+255)/256, 256>>>();
    k_gemm<128,0><<<gB, 256, sm128>>>(x, nullptr, W_emb, b_emb, nullptr, nullptr, nullptr, h);
    k_hist  <<<(EE+255)/256, 256>>>(ei);
    k_scan  <<<2, 1024>>>();
    k_fill  <<<(EE+255)/256, 256>>>(ei);
    k_dinv  <<<(NN+255)/256, 256>>>();
    k_e8agg <<<(NN*32+255)/256, 256>>>();
    k_gemm<128,0><<<gB, 256, sm128>>>(agg, nullptr, W_e8, nullptr, nullptr, nullptr, nullptr, xe8);
    k_gemm<128,0><<<gB, 256, sm128>>>(h, nullptr, W_gat, nullptr, nullptr, nullptr, nullptr, gg);
    k_att   <<<(NN*HEADS+255)/256, 256>>>(att_src, att_dst);
    k_gat   <<<(NN*32+255)/256, 256>>>(b_gat);
    k_gemm<256,1><<<gB, 256, sm256>>>(xe8, xgat, W_fus, b_fus, h, gamma, beta, z);
    k_readout<<<(NN+31)/32, 1024>>>(W_r1, b_r1, W_r2, b_r2, out);
}

// round 2
// speedup vs baseline: 1.2461x; 1.2461x over previous
#include <cuda_runtime.h>
#include <math.h>
#include <stdint.h>

#define NN   100000
#define EE   1600000
#define HID  128
#define HEADS 4
#define HDIM  32
#define NEG  0.2f
#define LNEPS 1e-5f

// ---------------- device scratch (no allocation allowed) ----------------
__device__ __align__(256) float g_h   [(size_t)NN*HID];
__device__ __align__(256) float g_agg [(size_t)NN*HID];
__device__ __align__(256) float g_xe8 [(size_t)NN*HID];
__device__ __align__(256) float g_gg  [(size_t)NN*HID];
__device__ __align__(256) float g_xgat[(size_t)NN*HID];
__device__ __align__(256) float g_z   [(size_t)NN*HID];
__device__ __align__(16)  float g_asrc[(size_t)NN*HEADS];
__device__ __align__(16)  float g_adst[(size_t)NN*HEADS];
__device__ float g_dinv[NN];
__device__ int   g_cnt_row[NN];
__device__ int   g_cnt_col[NN];
__device__ int   g_rptr[NN+1];
__device__ int   g_cptr[NN+1];
__device__ int   g_rcur[NN];
__device__ int   g_ccur[NN];
__device__ int   g_csr_rc[EE];
__device__ int   g_csr_cs[EE];
__device__ int   g_shift;

// ---------------- helpers ----------------
__device__ __forceinline__ float wsum(float x){
    #pragma unroll
    for (int o=16;o;o>>=1) x += __shfl_xor_sync(0xffffffffu, x, o);
    return x;
}
__device__ __forceinline__ float wmax(float x){
    #pragma unroll
    for (int o=16;o;o>>=1) x = fmaxf(x, __shfl_xor_sync(0xffffffffu, x, o));
    return x;
}
__device__ __forceinline__ float lrelu(float x){ return x > 0.f ? x : NEG * x; }

// packed f32x2 helpers (FFMA2 path — only reachable via PTX fma.rn.f32x2)
typedef unsigned long long ull;
__device__ __forceinline__ ull pack2(float x, float y){
    ull r; asm("mov.b64 %0, {%1,%2};" : "=l"(r) : "f"(x), "f"(y)); return r;
}
__device__ __forceinline__ void unpack2(ull v, float &x, float &y){
    asm("mov.b64 {%0,%1}, %2;" : "=f"(x), "=f"(y) : "l"(v));
}
__device__ __forceinline__ void ffma2(ull &d, ull a, ull b){
    asm("fma.rn.f32x2 %0, %1, %2, %0;" : "+l"(d) : "l"(a), "l"(b));
}

// ---------------- dtype detection ----------------
__global__ void k_detect(const int* ei){
    if (threadIdx.x == 0){
        int acc = 0;
        #pragma unroll 1
        for (int i = 1; i < 128; i += 2) acc |= ei[i];
        g_shift = (acc == 0) ? 1 : 0;
    }
}

__global__ void k_zero(){
    int i = blockIdx.x*blockDim.x + threadIdx.x;
    if (i < NN){ g_cnt_row[i]=0; g_cnt_col[i]=0; }
}

__global__ void k_hist(const int* ei){
    int e = blockIdx.x*blockDim.x + threadIdx.x;
    if (e >= EE) return;
    int sh = g_shift;
    int r = ei[(size_t)e << sh];
    int c = ei[(size_t)(EE + e) << sh];
    atomicAdd(&g_cnt_row[r], 1);
    atomicAdd(&g_cnt_col[c], 1);
}

__global__ void k_scan(){
    const int* cnt = blockIdx.x ? g_cnt_col : g_cnt_row;
    int* ptr = blockIdx.x ? g_cptr : g_rptr;
    int* cur = blockIdx.x ? g_ccur : g_rcur;
    __shared__ int sh[1024];
    __shared__ int carryS;
    int tid = threadIdx.x;
    int carry = 0;
    for (int base = 0; base < NN; base += 1024){
        int i = base + tid;
        int v = (i < NN) ? cnt[i] : 0;
        sh[tid] = v; __syncthreads();
        #pragma unroll
        for (int off = 1; off < 1024; off <<= 1){
            int t = (tid >= off) ? sh[tid-off] : 0;
            __syncthreads();
            sh[tid] += t;
            __syncthreads();
        }
        int inc = sh[tid];
        if (i < NN){ int ex = carry + inc - v; ptr[i] = ex; cur[i] = ex; }
        if (tid == 1023) carryS = carry + inc;
        __syncthreads();
        carry = carryS;
        __syncthreads();
    }
    if (tid == 0) ptr[NN] = carry;
}

__global__ void k_fill(const int* ei){
    int e = blockIdx.x*blockDim.x + threadIdx.x;
    if (e >= EE) return;
    int sh = g_shift;
    int r = ei[(size_t)e << sh];
    int c = ei[(size_t)(EE + e) << sh];
    int p = atomicAdd(&g_rcur[r], 1);
    g_csr_rc[p] = c;
    int q = atomicAdd(&g_ccur[c], 1);
    g_csr_cs[q] = r;
}

__global__ void k_dinv(){
    int i = blockIdx.x*blockDim.x + threadIdx.x;
    if (i < NN){
        int d = g_cnt_col[i];
        g_dinv[i] = d > 0 ? rsqrtf((float)d) : 0.f;
    }
}

// ---------------- FFMA2 GEMM: C[N,128] = A[N,KTOT] @ W[128,KTOT]^T (+bias)(+LN epi) ----
// 256 threads, 64 rows/block. K processed in 128-deep chunks (smem ~100KB -> 2 blk/SM).
// Warp: 8 rows x 128 cols; accumulators row-paired into f32x2.
#define WPAD 129
#define APAD 66
template<int KTOT, int EPI>
__global__ __launch_bounds__(256)
void k_gemm(const float* __restrict__ A0, const float* __restrict__ A1,
            const float* __restrict__ W,  const float* __restrict__ bias,
            const float* __restrict__ res, const float* __restrict__ gamma,
            const float* __restrict__ beta, float* __restrict__ C)
{
    extern __shared__ float smem[];
    float* Ws = smem;                 // [128][WPAD]
    float* As = smem + 128*WPAD;      // [128][APAD] transposed (k-major, rows inner)
    int tid  = threadIdx.x;
    int row0 = blockIdx.x * 64;
    int lane = tid & 31, warp = tid >> 5;
    int r0 = warp * 8;

    ull acc[4][4];
    #pragma unroll
    for (int p = 0; p < 4; p++)
        #pragma unroll
        for (int j = 0; j < 4; j++){
            float b = bias ? bias[lane + 32*j] : 0.f;
            acc[p][j] = pack2(b, b);
        }

    const int NCH = KTOT / 128;
    #pragma unroll
    for (int ch = 0; ch < NCH; ch++){
        const float* A = (NCH == 2 && ch == 1) ? A1 : A0;
        // W chunk: coalesced LDG, conflict-free STS (pad 129 => bank = (k+o)%32)
        for (int idx = tid; idx < 128*128; idx += 256){
            int o = idx >> 7, k = idx & 127;
            Ws[k*WPAD + o] = W[(size_t)o*KTOT + ch*128 + k];
        }
        // A chunk transposed: coalesced LDG, 2-way STS (pad 66)
        for (int idx = tid; idx < 64*128; idx += 256){
            int r = idx >> 7, k = idx & 127;
            int gr = row0 + r;
            As[k*APAD + r] = (gr < NN) ? A[(size_t)gr*128 + k] : 0.f;
        }
        __syncthreads();

        #pragma unroll 2
        for (int k = 0; k < 128; k++){
            const float* wr = Ws + k*WPAD + lane;
            ull w0 = pack2(wr[0],  wr[0]);
            ull w1 = pack2(wr[32], wr[32]);
            ull w2 = pack2(wr[64], wr[64]);
            ull w3 = pack2(wr[96], wr[96]);
            const ull* ar = (const ull*)(As + k*APAD + r0);
            ull a0 = ar[0], a1 = ar[1], a2 = ar[2], a3 = ar[3];
            ffma2(acc[0][0], a0, w0); ffma2(acc[0][1], a0, w1);
            ffma2(acc[0][2], a0, w2); ffma2(acc[0][3], a0, w3);
            ffma2(acc[1][0], a1, w0); ffma2(acc[1][1], a1, w1);
            ffma2(acc[1][2], a1, w2); ffma2(acc[1][3], a1, w3);
            ffma2(acc[2][0], a2, w0); ffma2(acc[2][1], a2, w1);
            ffma2(acc[2][2], a2, w2); ffma2(acc[2][3], a2, w3);
            ffma2(acc[3][0], a3, w0); ffma2(acc[3][1], a3, w1);
            ffma2(acc[3][2], a3, w2); ffma2(acc[3][3], a3, w3);
        }
        __syncthreads();
    }

    #pragma unroll
    for (int p = 0; p < 4; p++){
        float v0[4], v1[4];
        #pragma unroll
        for (int j = 0; j < 4; j++) unpack2(acc[p][j], v0[j], v1[j]);
        #pragma unroll
        for (int half = 0; half < 2; half++){
            float* v = half ? v1 : v0;
            int gr = row0 + r0 + 2*p + half;
            if (gr >= NN) continue;
            if (EPI == 0){
                #pragma unroll
                for (int j = 0; j < 4; j++)
                    C[(size_t)gr*128 + lane + 32*j] = v[j];
            } else {
                #pragma unroll
                for (int j = 0; j < 4; j++)
                    v[j] += res[(size_t)gr*128 + lane + 32*j];
                float s = v[0]+v[1]+v[2]+v[3];
                float mu = wsum(s) * (1.f/128.f);
                float q = 0.f;
                #pragma unroll
                for (int j = 0; j < 4; j++){ float d = v[j]-mu; q = fmaf(d,d,q); }
                float sc = rsqrtf(wsum(q) * (1.f/128.f) + LNEPS);
                #pragma unroll
                for (int j = 0; j < 4; j++){
                    int c = lane + 32*j;
                    float o = (v[j]-mu)*sc*gamma[c] + beta[c];
                    C[(size_t)gr*128 + c] = fmaxf(o, 0.f);
                }
            }
        }
    }
}

// ---------------- attention logits ----------------
__global__ void k_att(const float* __restrict__ att_src, const float* __restrict__ att_dst){
    int t = blockIdx.x*blockDim.x + threadIdx.x;
    if (t >= NN*HEADS) return;
    int n = t >> 2, h = t & 3;
    const float* gp = &g_gg[(size_t)n*128 + h*32];
    float s = 0.f, d = 0.f;
    #pragma unroll
    for (int c = 0; c < 32; c++){
        float gv = gp[c];
        s = fmaf(gv, att_src[h*32+c], s);
        d = fmaf(gv, att_dst[h*32+c], d);
    }
    g_asrc[t] = s; g_adst[t] = d;
}

// ---------------- E8 aggregation ----------------
__global__ void k_e8agg(){
    int w = (blockIdx.x*blockDim.x + threadIdx.x) >> 5;
    if (w >= NN) return;
    int lane = threadIdx.x & 31;
    int s = g_rptr[w], e = g_rptr[w+1];
    float4 acc = make_float4(0.f,0.f,0.f,0.f);
    #pragma unroll 2
    for (int i = s; i < e; i++){
        int c = g_csr_rc[i];
        float dv = g_dinv[c];
        float4 hv = ((const float4*)(g_h + (size_t)c*128))[lane];
        acc.x = fmaf(dv, hv.x, acc.x);
        acc.y = fmaf(dv, hv.y, acc.y);
        acc.z = fmaf(dv, hv.z, acc.z);
        acc.w = fmaf(dv, hv.w, acc.w);
    }
    float du = g_dinv[w];
    float4 o = make_float4(du*acc.x, du*acc.y, du*acc.z, du*acc.w);
    ((float4*)(g_agg + (size_t)w*128))[lane] = o;
}

// ---------------- GAT ----------------
__global__ void k_gat(const float* __restrict__ bgat){
    int v = (blockIdx.x*blockDim.x + threadIdx.x) >> 5;
    if (v >= NN) return;
    int lane = threadIdx.x & 31;
    int s = g_cptr[v], e = g_cptr[v+1];

    float4 ad = ((const float4*)g_adst)[v];
    float4 asl = ((const float4*)g_asrc)[v];
    float es0 = lrelu(asl.x + ad.x), es1 = lrelu(asl.y + ad.y);
    float es2 = lrelu(asl.z + ad.z), es3 = lrelu(asl.w + ad.w);

    float m0 = es0, m1 = es1, m2 = es2, m3 = es3;
    for (int i = s + lane; i < e; i += 32){
        int u = g_csr_cs[i];
        float4 a = ((const float4*)g_asrc)[u];
        m0 = fmaxf(m0, lrelu(a.x + ad.x));
        m1 = fmaxf(m1, lrelu(a.y + ad.y));
        m2 = fmaxf(m2, lrelu(a.z + ad.z));
        m3 = fmaxf(m3, lrelu(a.w + ad.w));
    }
    m0 = wmax(m0); m1 = wmax(m1); m2 = wmax(m2); m3 = wmax(m3);

    float s0=0.f,s1=0.f,s2=0.f,s3=0.f;
    for (int i = s + lane; i < e; i += 32){
        int u = g_csr_cs[i];
        float4 a = ((const float4*)g_asrc)[u];
        s0 += __expf(lrelu(a.x + ad.x) - m0);
        s1 += __expf(lrelu(a.y + ad.y) - m1);
        s2 += __expf(lrelu(a.z + ad.z) - m2);
        s3 += __expf(lrelu(a.w + ad.w) - m3);
    }
    s0 = wsum(s0) + __expf(es0 - m0);
    s1 = wsum(s1) + __expf(es1 - m1);
    s2 = wsum(s2) + __expf(es2 - m2);
    s3 = wsum(s3) + __expf(es3 - m3);
    float i0 = 1.f/(s0+1e-16f), i1 = 1.f/(s1+1e-16f), i2 = 1.f/(s2+1e-16f), i3 = 1.f/(s3+1e-16f);

    int hidx = lane >> 3;
    float adh  = (hidx==0)?ad.x : (hidx==1)?ad.y : (hidx==2)?ad.z : ad.w;
    float mh   = (hidx==0)?m0  : (hidx==1)?m1  : (hidx==2)?m2  : m3;
    float ih   = (hidx==0)?i0  : (hidx==1)?i1  : (hidx==2)?i2  : i3;
    float esh  = (hidx==0)?es0 : (hidx==1)?es1 : (hidx==2)?es2 : es3;

    float4 acc = make_float4(0.f,0.f,0.f,0.f);
    #pragma unroll 2
    for (int i = s; i < e; i++){
        int u = g_csr_cs[i];
        float a = g_asrc[(size_t)u*4 + hidx];
        float alpha = __expf(lrelu(a + adh) - mh) * ih;
        float4 gv = ((const float4*)(g_gg + (size_t)u*128))[lane];
        acc.x = fmaf(alpha, gv.x, acc.x);
        acc.y = fmaf(alpha, gv.y, acc.y);
        acc.z = fmaf(alpha, gv.z, acc.z);
        acc.w = fmaf(alpha, gv.w, acc.w);
    }
    {
        float alpha = __expf(esh - mh) * ih;
        float4 gv = ((const float4*)(g_gg + (size_t)v*128))[lane];
        acc.x = fmaf(alpha, gv.x, acc.x);
        acc.y = fmaf(alpha, gv.y, acc.y);
        acc.z = fmaf(alpha, gv.z, acc.z);
        acc.w = fmaf(alpha, gv.w, acc.w);
    }
    float4 b = ((const float4*)bgat)[lane];
    acc.x += b.x; acc.y += b.y; acc.z += b.z; acc.w += b.w;
    ((float4*)(g_xgat + (size_t)v*128))[lane] = acc;
}

// ---------------- fused readout (FFMA2, col-paired accumulator) -----------------
__global__ __launch_bounds__(1024)
void k_readout(const float* __restrict__ Wr1, const float* __restrict__ br1,
               const float* __restrict__ Wr2, const float* __restrict__ br2,
               float* __restrict__ out)
{
    __shared__ ull Ws2[128*32];   // Ws2[k*32+o] = (Wr1[o][k], Wr1[o+32][k])
    int tid = threadIdx.x;
    for (int idx = tid; idx < 128*32; idx += 1024){
        int k = idx >> 5, o = idx & 31;
        Ws2[idx] = pack2(Wr1[(size_t)o*128 + k], Wr1[(size_t)(o+32)*128 + k]);
    }
    __syncthreads();
    int warp = tid >> 5, lane = tid & 31;
    int node = blockIdx.x*32 + warp;
    if (node >= NN) return;

    float4 zv = ((const float4*)(g_z + (size_t)node*128))[lane];
    ull acc = pack2(br1[lane], br1[lane+32]);
    #pragma unroll 8
    for (int kb = 0; kb < 32; kb++){
        float zx = __shfl_sync(0xffffffffu, zv.x, kb);
        float zy = __shfl_sync(0xffffffffu, zv.y, kb);
        float zz = __shfl_sync(0xffffffffu, zv.z, kb);
        float zw = __shfl_sync(0xffffffffu, zv.w, kb);
        int k = kb*4;
        ffma2(acc, pack2(zx,zx), Ws2[(k+0)*32+lane]);
        ffma2(acc, pack2(zy,zy), Ws2[(k+1)*32+lane]);
        ffma2(acc, pack2(zz,zz), Ws2[(k+2)*32+lane]);
        ffma2(acc, pack2(zw,zw), Ws2[(k+3)*32+lane]);
    }
    float a0, a1; unpack2(acc, a0, a1);
    float r0 = fmaxf(a0, 0.f);
    float r1 = fmaxf(a1, 0.f);
    float p = fmaf(r0, Wr2[lane], r1 * Wr2[lane+32]);
    p = wsum(p);
    if (lane == 0){
        float x = p + br2[0];
        out[node] = 1.f / (1.f + __expf(-x));
    }
}

// ---------------- host ----------------
extern "C" void kernel_launch(void* const* d_in, const int* in_sizes, int n_in,
                              void* d_out, int out_size)
{
    const float* x       = (const float*)d_in[0];
    const int*   ei      = (const int*)  d_in[1];
    const float* W_emb   = (const float*)d_in[2];
    const float* b_emb   = (const float*)d_in[3];
    const float* W_e8    = (const float*)d_in[4];
    const float* W_gat   = (const float*)d_in[5];
    const float* att_src = (const float*)d_in[6];
    const float* att_dst = (const float*)d_in[7];
    const float* b_gat   = (const float*)d_in[8];
    const float* W_fus   = (const float*)d_in[9];
    const float* b_fus   = (const float*)d_in[10];
    const float* gamma   = (const float*)d_in[11];
    const float* beta    = (const float*)d_in[12];
    const float* W_r1    = (const float*)d_in[13];
    const float* b_r1    = (const float*)d_in[14];
    const float* W_r2    = (const float*)d_in[15];
    const float* b_r2    = (const float*)d_in[16];
    float* out = (float*)d_out;

    float *h, *agg, *xe8, *gg, *xgat, *z;
    cudaGetSymbolAddress((void**)&h,    g_h);
    cudaGetSymbolAddress((void**)&agg,  g_agg);
    cudaGetSymbolAddress((void**)&xe8,  g_xe8);
    cudaGetSymbolAddress((void**)&gg,   g_gg);
    cudaGetSymbolAddress((void**)&xgat, g_xgat);
    cudaGetSymbolAddress((void**)&z,    g_z);

    int smB = (128*WPAD + 128*APAD) * 4;   // ~100KB, chunked for all K
    cudaFuncSetAttribute(k_gemm<128,0>, cudaFuncAttributeMaxDynamicSharedMemorySize, smB);
    cudaFuncSetAttribute(k_gemm<256,1>, cudaFuncAttributeMaxDynamicSharedMemorySize, smB);

    int gB = (NN + 63) / 64;

    k_detect<<<1, 32>>>(ei);
    k_zero  <<<(NN+255)/256, 256>>>();
    k_gemm<128,0><<<gB, 256, smB>>>(x, nullptr, W_emb, b_emb, nullptr, nullptr, nullptr, h);
    k_hist  <<<(EE+255)/256, 256>>>(ei);
    k_scan  <<<2, 1024>>>();
    k_fill  <<<(EE+255)/256, 256>>>(ei);
    k_dinv  <<<(NN+255)/256, 256>>>();
    k_e8agg <<<(NN*32+255)/256, 256>>>();
    k_gemm<128,0><<<gB, 256, smB>>>(agg, nullptr, W_e8, nullptr, nullptr, nullptr, nullptr, xe8);
    k_gemm<128,0><<<gB, 256, smB>>>(h, nullptr, W_gat, nullptr, nullptr, nullptr, nullptr, gg);
    k_att   <<<(NN*HEADS+255)/256, 256>>>(att_src, att_dst);
    k_gat   <<<(NN*32+255)/256, 256>>>(b_gat);
    k_gemm<256,1><<<gB, 256, smB>>>(xe8, xgat, W_fus, b_fus, h, gamma, beta, z);
    k_readout<<<(NN+31)/32, 1024>>>(W_r1, b_r1, W_r2, b_r2, out);
}